// round 7
// baseline (speedup 1.0000x reference)
#include <cuda_runtime.h>
#include <math.h>

#define ISZ    256
#define TILE   16
#define NEARP  0.1f
#define FARP   100.0f
#define EPSP   0.001f
#define TINYF  1e-12f
#define MAXF_TOT 32768
#define MAXTILES 2048         // up to B=8 batches of 16x16 tiles
#define TCAP   640

// Per-face edge coefficients: (Ak, Bk, Ck, 1/zk) for k=0,1,2
__device__ float4       g_coef[MAXF_TOT * 3];
// Per-tile face lists built by the pre-pass
__device__ unsigned int g_list[MAXTILES * TCAP];
__device__ int          g_cnt[MAXTILES];

__global__ void zero_kernel(int ntiles)
{
    int i = blockIdx.x * blockDim.x + threadIdx.x;
    if (i < ntiles) g_cnt[i] = 0;
}

__global__ void pre_kernel(const float* __restrict__ faces, int F, int B)
{
    int i = blockIdx.x * blockDim.x + threadIdx.x;
    if (i >= B * F) return;
    const int b = i / F;
    const int f = i - b * F;

    const float* fp = faces + (size_t)i * 9;
    const float x0 = fp[0], y0 = fp[1], z0 = fp[2];
    const float x1 = fp[3], y1 = fp[4], z1 = fp[5];
    const float x2 = fp[6], y2 = fp[7], z2 = fp[8];

    // w_k = A_k*yp + B_k*xp + C_k  (identical expressions to the passing kernel)
    g_coef[i * 3 + 0] = make_float4(x2 - x1, y1 - y2, x1 * y2 - x2 * y1, 1.0f / z0);
    g_coef[i * 3 + 1] = make_float4(x0 - x2, y2 - y0, x2 * y0 - x0 * y2, 1.0f / z1);
    g_coef[i * 3 + 2] = make_float4(x1 - x0, y0 - y1, x0 * y1 - x1 * y0, 1.0f / z2);

    const float mnx = fminf(x0, fminf(x1, x2));
    const float mxx = fmaxf(x0, fmaxf(x1, x2));
    const float mny = fminf(y0, fminf(y1, y2));
    const float mxy = fmaxf(y0, fmaxf(y1, y2));

    // Widened pixel range (same formulas as the round-5 rasterizer clip)
    int px0 = (int)floorf(fmaf(128.f, mnx, 127.5f));
    int px1 = (int)floorf(fmaf(128.f, mxx, 127.5f)) + 1;
    int py0 = (int)floorf(fmaf(128.f, mny, 127.5f));
    int py1 = (int)floorf(fmaf(128.f, mxy, 127.5f)) + 1;
    px0 = max(px0, 0); py0 = max(py0, 0);
    px1 = min(px1, ISZ - 1); py1 = min(py1, ISZ - 1);
    if (px0 > px1 || py0 > py1) return;

    const int txl = px0 >> 4, txh = px1 >> 4;
    const int tyl = py0 >> 4, tyh = py1 >> 4;
    for (int ty = tyl; ty <= tyh; ty++) {
        for (int tx = txl; tx <= txh; tx++) {
            const int gx = tx << 4, gy = ty << 4;
            const int l0 = max(px0, gx) - gx;
            const int l1 = min(px1, gx + 15) - gx;
            const int m0 = max(py0, gy) - gy;
            const int m1 = min(py1, gy + 15) - gy;
            const unsigned int entry =
                ((unsigned int)f << 16) | (l0 << 12) | (l1 << 8) | (m0 << 4) | m1;
            const int tile = b * 256 + ty * 16 + tx;
            const int p = atomicAdd(&g_cnt[tile], 1);
            if (p < TCAP) g_list[tile * TCAP + p] = entry;
        }
    }
}

__global__ __launch_bounds__(TILE * TILE, 8)
void rast_kernel(const float* __restrict__ faces,
                 const float* __restrict__ tex,
                 float* __restrict__ out,
                 int F, int T)
{
    __shared__ unsigned long long zb[TILE * TILE];
    __shared__ int scur;

    const int b    = blockIdx.z;
    const int tid  = threadIdx.x;
    const int lane = tid & 31;
    const int tx0  = blockIdx.x * TILE;
    const int ty0  = blockIdx.y * TILE;
    const int tile = b * 256 + blockIdx.y * 16 + blockIdx.x;
    const int bofs = b * F;

    const float inv_is = 1.0f / (float)ISZ;

    if (tid == 0) scur = 0;
    zb[tid] = (((unsigned long long)__float_as_uint(FARP)) << 32) | 0xFFFFFFFFull;
    __syncthreads();

    // ---- Rasterize: warp-per-face with work-stealing over the precomputed list ----
    const int cnt = min(g_cnt[tile], TCAP);
    const unsigned int* list = &g_list[tile * TCAP];
    for (;;) {
        int i;
        if (lane == 0) i = atomicAdd(&scur, 1);
        i = __shfl_sync(0xFFFFFFFFu, i, 0);
        if (i >= cnt) break;

        const unsigned int entry = list[i];
        const int fidx = entry >> 16;
        const int px0  = tx0 + ((entry >> 12) & 15);
        const int px1  = tx0 + ((entry >> 8) & 15);
        const int py0  = ty0 + ((entry >> 4) & 15);
        const int py1  = ty0 + (entry & 15);

        const float4 e0 = g_coef[(bofs + fidx) * 3 + 0];
        const float4 e1 = g_coef[(bofs + fidx) * 3 + 1];
        const float4 e2 = g_coef[(bofs + fidx) * 3 + 2];

        const int w   = px1 - px0 + 1;
        const int h   = py1 - py0 + 1;
        const int npx = w * h;
        // exact n/w for n,w < 2^16 via magic multiply (w==1 handled separately)
        const unsigned int magic = (w > 1) ? (0xFFFFFFFFu / (unsigned)w + 1u) : 0u;

        for (int j = lane; j < npx; j += 32) {
            const int row = (w > 1) ? (int)__umulhi((unsigned)j, magic) : j;
            const int col = j - row * w;
            const int px = px0 + col;
            const int py = py0 + row;
            const float xp = (2.0f * px + 1.0f - ISZ) * inv_is;
            const float yp = (2.0f * py + 1.0f - ISZ) * inv_is;

            const float w0 = fmaf(e0.x, yp, fmaf(e0.y, xp, e0.z));
            const float w1 = fmaf(e1.x, yp, fmaf(e1.y, xp, e1.z));
            const float w2 = fmaf(e2.x, yp, fmaf(e2.y, xp, e2.z));
            const float det = w0 + w1 + w2;
            const bool ins = (w0 > 0.f && w1 > 0.f && w2 > 0.f && det >  TINYF) ||
                             (w0 < 0.f && w1 < 0.f && w2 < 0.f && det < -TINYF);
            if (ins) {
                const float hh = fmaf(w0, e0.w, fmaf(w1, e1.w, w2 * e2.w));
                const float zp = det / hh;
                if (zp > NEARP && zp < FARP) {
                    const unsigned long long key =
                        (((unsigned long long)__float_as_uint(zp)) << 32) | (unsigned int)fidx;
                    atomicMin(&zb[(py - ty0) * TILE + (px - tx0)], key);
                }
            }
        }
    }
    __syncthreads();

    // ---- Shading pass: exact reference math on the winning face ----
    const int lx = tid & (TILE - 1);
    const int ly = tid >> 4;
    const int px = tx0 + lx;
    const int py = ty0 + ly;
    const float xp = (2.0f * px + 1.0f - ISZ) * inv_is;
    const float yp = (2.0f * py + 1.0f - ISZ) * inv_is;

    const unsigned long long key = zb[tid];
    const unsigned int idxbits = (unsigned int)(key & 0xFFFFFFFFull);
    const int bestf = (int)idxbits;
    const bool hit = (idxbits != 0xFFFFFFFFu);

    float r = 0.f, g = 0.f, bl = 0.f, alpha = 0.f, depth = FARP;

    if (hit) {
        const float* fp = faces + ((size_t)b * F + bestf) * 9;
        const float x0 = fp[0], y0 = fp[1], z0 = fp[2];
        const float x1 = fp[3], y1 = fp[4], z1 = fp[5];
        const float x2 = fp[6], y2 = fp[7], z2 = fp[8];

        const float w0 = yp * (x2 - x1) + xp * (y1 - y2) + (x1 * y2 - x2 * y1);
        const float w1 = yp * (x0 - x2) + xp * (y2 - y0) + (x2 * y0 - x0 * y2);
        const float w2 = yp * (x1 - x0) + xp * (y0 - y1) + (x0 * y1 - x1 * y0);
        const float det = w0 + w1 + w2;
        const float sd  = (fabsf(det) > TINYF) ? det : 1.0f;
        float n0 = w0 / sd, n1 = w1 / sd, n2 = w2 / sd;
        n0 = fminf(fmaxf(n0, 0.f), 1.f);
        n1 = fminf(fmaxf(n1, 0.f), 1.f);
        n2 = fminf(fmaxf(n2, 0.f), 1.f);
        float s = n0 + n1 + n2;
        s = (s > TINYF) ? s : 1.0f;
        n0 /= s; n1 /= s; n2 /= s;
        float inv = n0 / z0 + n1 / z1 + n2 / z2;
        inv = (fabsf(inv) > TINYF) ? inv : 1.0f;
        const float zp2 = 1.0f / inv;
        depth = zp2;
        alpha = 1.0f;

        const float Tm1  = (float)(T - 1);
        const float tmax = Tm1 - EPSP;
        float t0 = n0 * Tm1 * zp2 / z0;
        float t1 = n1 * Tm1 * zp2 / z1;
        float t2 = n2 * Tm1 * zp2 / z2;
        t0 = fminf(fmaxf(t0, 0.f), tmax);
        t1 = fminf(fmaxf(t1, 0.f), tmax);
        t2 = fminf(fmaxf(t2, 0.f), tmax);
        const int l0 = (int)floorf(t0);
        const int l1 = (int)floorf(t1);
        const int l2 = (int)floorf(t2);
        const float f0 = t0 - (float)l0;
        const float f1 = t1 - (float)l1;
        const float f2 = t2 - (float)l2;

        const float* tb = tex + (((size_t)b * F + bestf) * T * T * T) * 3;

        #pragma unroll
        for (int d0 = 0; d0 < 2; d0++) {
            const float wa = d0 ? f0 : (1.0f - f0);
            #pragma unroll
            for (int d1 = 0; d1 < 2; d1++) {
                const float wb = wa * (d1 ? f1 : (1.0f - f1));
                #pragma unroll
                for (int d2 = 0; d2 < 2; d2++) {
                    const float wgt = wb * (d2 ? f2 : (1.0f - f2));
                    const float* sp = tb + ((((l0 + d0) * T) + (l1 + d1)) * T + (l2 + d2)) * 3;
                    r  += wgt * sp[0];
                    g  += wgt * sp[1];
                    bl += wgt * sp[2];
                }
            }
        }
    }

    const size_t o = (((size_t)b * ISZ + py) * ISZ + px) * 5;
    out[o + 0] = r;
    out[o + 1] = g;
    out[o + 2] = bl;
    out[o + 3] = alpha;
    out[o + 4] = depth;
}

extern "C" void kernel_launch(void* const* d_in, const int* in_sizes, int n_in,
                              void* d_out, int out_size)
{
    const float* faces = (const float*)d_in[0];
    const float* tex   = (const float*)d_in[1];
    int fsz = in_sizes[0];
    int tsz = in_sizes[1];
    if (fsz > tsz) {  // be robust to input ordering
        const float* tmp = faces; faces = tex; tex = tmp;
        int t = fsz; fsz = tsz; tsz = t;
    }

    const int B = out_size / (ISZ * ISZ * 5);
    const int F = fsz / (B * 9);
    const int t3 = tsz / (B * F * 3);
    int T = 1;
    while (T * T * T < t3) T++;

    const int ntiles = B * 256;
    zero_kernel<<<(ntiles + 255) / 256, 256>>>(ntiles);

    const int total = B * F;  // 16384 for this problem; scratch sized 32768
    pre_kernel<<<(total + 255) / 256, 256>>>(faces, F, B);

    dim3 grid(ISZ / TILE, ISZ / TILE, B);
    dim3 block(TILE * TILE);
    rast_kernel<<<grid, block>>>(faces, tex, (float*)d_out, F, T);
}